// round 1
// baseline (speedup 1.0000x reference)
#include <cuda_runtime.h>
#include <math.h>

#define H 256
#define W 256
#define HW 65536
#define BATCH 4
#define NSTAT (BATCH*HW)   // 262144 elements per channel for BN
#define SLICES 64

#define SZ16 (BATCH*16*HW)
#define SZ18 (BATCH*18*HW)
#define SZ32 (BATCH*32*HW)
#define SZ64 (BATCH*64*HW)

// ---------------- scratch (static device globals; no allocations) ----------
__device__ float g_hf[SZ16];
__device__ float g_pre[SZ16];
__device__ float g_t[SZ16];
__device__ float g_cat[SZ32];
__device__ float g_off[SZ18];
__device__ float g_d16[SZ16];
__device__ float g_d16b[SZ16];
__device__ float g_d64[SZ64];
__device__ float g_d64b[SZ64];
__device__ float g_xxs[SZ64];
__device__ float g_sp[BATCH*2*HW];
__device__ float g_xb[4][SZ16];
__device__ float g_psum[64*SLICES];
__device__ float g_psq[64*SLICES];
__device__ float g_mean[64];
__device__ float g_inv[64];
__device__ float g_avg[BATCH*64];
__device__ float g_gmax[BATCH*64];
__device__ float g_ca[BATCH*64];

// ---------------- BN statistics (deterministic two-stage) ------------------
__global__ void stats_part_k(const float* __restrict__ x, int C,
                             float* __restrict__ psum, float* __restrict__ psq)
{
    int s = blockIdx.x, c = blockIdx.y;
    const int L = NSTAT / SLICES; // 4096
    float sm = 0.f, sq = 0.f;
    for (int k = threadIdx.x; k < L; k += blockDim.x) {
        int e = s * L + k;
        int b = e >> 16, pix = e & (HW - 1);
        float v = x[(size_t)(b * C + c) * HW + pix];
        sm += v; sq += v * v;
    }
    __shared__ float ssm[256], ssq[256];
    ssm[threadIdx.x] = sm; ssq[threadIdx.x] = sq;
    __syncthreads();
    for (int off = 128; off > 0; off >>= 1) {
        if (threadIdx.x < off) {
            ssm[threadIdx.x] += ssm[threadIdx.x + off];
            ssq[threadIdx.x] += ssq[threadIdx.x + off];
        }
        __syncthreads();
    }
    if (threadIdx.x == 0) {
        psum[c * SLICES + s] = ssm[0];
        psq[c * SLICES + s]  = ssq[0];
    }
}

__global__ void stats_final_k(int C, const float* __restrict__ psum,
                              const float* __restrict__ psq,
                              float* __restrict__ mean, float* __restrict__ inv)
{
    int c = threadIdx.x;
    if (c < C) {
        float sm = 0.f, sq = 0.f;
        for (int s = 0; s < SLICES; s++) { sm += psum[c*SLICES+s]; sq += psq[c*SLICES+s]; }
        float m = sm / (float)NSTAT;
        float v = sq / (float)NSTAT - m * m;
        mean[c] = m;
        inv[c] = rsqrtf(v + 1e-5f);
    }
}

// out = [relu?]((x - mean)*invstd) [+ add1][+ add2]
template<bool RELU>
__global__ void norm_k(const float* __restrict__ x, float* __restrict__ out, int C, int n,
                       const float* __restrict__ mean, const float* __restrict__ inv,
                       const float* __restrict__ add1, int a1Ct, int a1Co,
                       const float* __restrict__ add2, int a2Ct, int a2Co)
{
    int idx = blockIdx.x * blockDim.x + threadIdx.x;
    if (idx >= n) return;
    int pix = idx & (HW - 1);
    int rest = idx >> 16;
    int c = rest % C;
    int b = rest / C;
    float v = (x[idx] - __ldg(&mean[c])) * __ldg(&inv[c]);
    if (RELU) v = fmaxf(v, 0.f);
    if (add1) v += add1[(size_t)(b * a1Ct + a1Co + c) * HW + pix];
    if (add2) v += add2[(size_t)(b * a2Ct + a2Co + c) * HW + pix];
    out[idx] = v;
}

// ---------------- 1x1 convs -------------------------------------------------
__global__ void __launch_bounds__(256) conv1x1_64_16_k(
    const float* __restrict__ in, const float* __restrict__ w,
    const float* __restrict__ bias, float* __restrict__ out)
{
    __shared__ __align__(16) float ws[64*16];
    for (int i = threadIdx.x; i < 64*16; i += blockDim.x) {
        int o = i & 15, c = i >> 4;
        ws[i] = w[o * 64 + c];           // ws[c*16+o]
    }
    __syncthreads();
    int pix = blockIdx.x * blockDim.x + threadIdx.x;
    int b = blockIdx.y;
    float acc[16];
    #pragma unroll
    for (int o = 0; o < 16; o++) acc[o] = __ldg(&bias[o]);
    for (int c = 0; c < 64; c++) {
        float v = in[(size_t)(b * 64 + c) * HW + pix];
        const float4* wr = (const float4*)&ws[c * 16];
        #pragma unroll
        for (int o4 = 0; o4 < 4; o4++) {
            float4 wv = wr[o4];
            acc[4*o4+0] = fmaf(v, wv.x, acc[4*o4+0]);
            acc[4*o4+1] = fmaf(v, wv.y, acc[4*o4+1]);
            acc[4*o4+2] = fmaf(v, wv.z, acc[4*o4+2]);
            acc[4*o4+3] = fmaf(v, wv.w, acc[4*o4+3]);
        }
    }
    #pragma unroll
    for (int o = 0; o < 16; o++) out[(size_t)(b * 16 + o) * HW + pix] = acc[o];
}

__global__ void __launch_bounds__(256) conv1x1_cat4_k(
    const float* __restrict__ x0, const float* __restrict__ x1,
    const float* __restrict__ x2, const float* __restrict__ x3,
    const float* __restrict__ w, const float* __restrict__ bias,
    float* __restrict__ out)
{
    __shared__ __align__(16) float ws[64*64];
    for (int i = threadIdx.x; i < 64*64; i += blockDim.x) {
        int o = i & 63, c = i >> 6;
        ws[i] = w[o * 64 + c];           // ws[c*64+o]
    }
    __syncthreads();
    int pix = blockIdx.x * blockDim.x + threadIdx.x;
    int b = blockIdx.y;
    float acc[64];
    #pragma unroll
    for (int o = 0; o < 64; o++) acc[o] = __ldg(&bias[o]);
    const float* srcs[4] = {x0, x1, x2, x3};
    for (int s = 0; s < 4; s++) {
        const float* sp_ = srcs[s] + (size_t)b * 16 * HW + pix;
        for (int c = 0; c < 16; c++) {
            float v = sp_[(size_t)c * HW];
            const float4* wr = (const float4*)&ws[(s * 16 + c) * 64];
            #pragma unroll
            for (int o4 = 0; o4 < 16; o4++) {
                float4 wv = wr[o4];
                acc[4*o4+0] = fmaf(v, wv.x, acc[4*o4+0]);
                acc[4*o4+1] = fmaf(v, wv.y, acc[4*o4+1]);
                acc[4*o4+2] = fmaf(v, wv.z, acc[4*o4+2]);
                acc[4*o4+3] = fmaf(v, wv.w, acc[4*o4+3]);
            }
        }
    }
    #pragma unroll
    for (int o = 0; o < 64; o++) out[(size_t)(b * 64 + o) * HW + pix] = acc[o];
}

// copy concat([A_view(16ch), B(16ch)]) -> dst(32ch)
__global__ void cat2_k(const float* __restrict__ A, int aCt, int aCo,
                       const float* __restrict__ Bp, float* __restrict__ dst)
{
    int idx = blockIdx.x * blockDim.x + threadIdx.x; // BATCH*32*HW
    int pix = idx & (HW - 1);
    int rest = idx >> 16;
    int c = rest & 31;
    int b = rest >> 5;
    float v = (c < 16) ? A[(size_t)(b * aCt + aCo + c) * HW + pix]
                       : Bp[(size_t)(b * 16 + (c - 16)) * HW + pix];
    dst[idx] = v;
}

// ---------------- generic 3x3 conv ------------------------------------------
template<int CIN, int COUT, bool BIAS>
__global__ void __launch_bounds__(256) conv3x3_k(
    const float* __restrict__ in, int inCt, int inCo,
    const float* __restrict__ w, const float* __restrict__ bias,
    float* __restrict__ out, int dil)
{
    constexpr int CCHUNK = (CIN < 16) ? CIN : 16;
    constexpr int WSZ = CCHUNK * COUT * 9;
    __shared__ __align__(16) float ws[WSZ];
    int pix = blockIdx.x * blockDim.x + threadIdx.x;
    int b = blockIdx.y;
    int y = pix >> 8, x = pix & 255;

    float acc[COUT];
    #pragma unroll
    for (int o = 0; o < COUT; o++) acc[o] = BIAS ? __ldg(&bias[o]) : 0.f;

    for (int c0 = 0; c0 < CIN; c0 += CCHUNK) {
        __syncthreads();
        for (int i = threadIdx.x; i < WSZ; i += blockDim.x) {
            int o = i % COUT;
            int rem = i / COUT;
            int k = rem % 9;
            int cl = rem / 9;
            ws[i] = w[(size_t)(o * CIN + c0 + cl) * 9 + k]; // ws[(cl*9+k)*COUT+o]
        }
        __syncthreads();
        #pragma unroll 1
        for (int cl = 0; cl < CCHUNK; cl++) {
            const float* inp = in + (size_t)(b * inCt + inCo + c0 + cl) * HW;
            #pragma unroll
            for (int ky = 0; ky < 3; ky++) {
                int yy = y + (ky - 1) * dil;
                bool oky = ((unsigned)yy < (unsigned)H);
                #pragma unroll
                for (int kx = 0; kx < 3; kx++) {
                    int xx = x + (kx - 1) * dil;
                    float v = (oky && (unsigned)xx < (unsigned)W) ? inp[yy * W + xx] : 0.f;
                    const float* wrow = &ws[(cl * 9 + ky * 3 + kx) * COUT];
                    if (COUT % 4 == 0) {
                        #pragma unroll
                        for (int o4 = 0; o4 < COUT / 4; o4++) {
                            float4 wv = *(const float4*)(wrow + 4 * o4);
                            acc[4*o4+0] = fmaf(v, wv.x, acc[4*o4+0]);
                            acc[4*o4+1] = fmaf(v, wv.y, acc[4*o4+1]);
                            acc[4*o4+2] = fmaf(v, wv.z, acc[4*o4+2]);
                            acc[4*o4+3] = fmaf(v, wv.w, acc[4*o4+3]);
                        }
                    } else {
                        #pragma unroll
                        for (int o = 0; o < COUT; o++)
                            acc[o] = fmaf(v, wrow[o], acc[o]);
                    }
                }
            }
        }
    }
    #pragma unroll
    for (int o = 0; o < COUT; o++) out[(size_t)(b * COUT + o) * HW + pix] = acc[o];
}

// ---------------- deformable conv (exact reference semantics) ---------------
__global__ void __launch_bounds__(256) deform_k(
    const float* __restrict__ t, const float* __restrict__ off,
    const float* __restrict__ wd, float* __restrict__ out)
{
    __shared__ __align__(16) float ws[16*16*9]; // ws[(c*9+n)*16+o]
    for (int i = threadIdx.x; i < 2304; i += blockDim.x) {
        int o = i & 15;
        int rem = i >> 4;
        int n = rem % 9;
        int c = rem / 9;
        ws[i] = wd[(o * 16 + c) * 9 + n];
    }
    __syncthreads();
    int pix = blockIdx.x * blockDim.x + threadIdx.x;
    int b = blockIdx.y;
    int yi = pix >> 8, xj = pix & 255;

    float acc[16];
    #pragma unroll
    for (int o = 0; o < 16; o++) acc[o] = 0.f;

    const float* offb = off + (size_t)b * 18 * HW + pix;
    const float* tb = t + (size_t)b * 16 * HW;

    #pragma unroll 1
    for (int n = 0; n < 9; n++) {
        int dx = n / 3 - 1, dy = n % 3 - 1;
        float ox = offb[(size_t)(2 * n) * HW];
        float oy = offb[(size_t)(2 * n + 1) * HW];
        float plx = (float)(yi + 1 + dx) + ox;   // coordinates in padded (258x258) frame
        float ply = (float)(xj + 1 + dy) + oy;
        float flx = floorf(plx), fly = floorf(ply);
        int qltx = min(max((int)flx, 0), 257);
        int qlty = min(max((int)fly, 0), 257);
        int qrbx = min(max((int)flx + 1, 0), 257);
        int qrby = min(max((int)fly + 1, 0), 257);
        bool mx = (plx < 1.0f) || (plx > 256.0f);
        bool my = (ply < 1.0f) || (ply > 256.0f);
        float px = mx ? flx : plx; px = fminf(fmaxf(px, 0.f), 257.f);
        float py = my ? fly : ply; py = fminf(fmaxf(py, 0.f), 257.f);
        float wltx = 1.f + ((float)qltx - px);
        float wrbx = 1.f - ((float)qrbx - px);
        float wlty = 1.f + ((float)qlty - py);
        float wrby = 1.f - ((float)qrby - py);
        float glt = wltx * wlty, grb = wrbx * wrby;
        float glb = wltx * wrby, grt = wrbx * wlty;
        bool vltx = (qltx >= 1 && qltx <= 256);
        bool vlty = (qlty >= 1 && qlty <= 256);
        bool vrbx = (qrbx >= 1 && qrbx <= 256);
        bool vrby = (qrby >= 1 && qrby <= 256);
        int rlt = (qltx - 1) * W + (qlty - 1);
        int rrb = (qrbx - 1) * W + (qrby - 1);
        int rlb = (qltx - 1) * W + (qrby - 1);
        int rrt = (qrbx - 1) * W + (qlty - 1);
        #pragma unroll 1
        for (int c = 0; c < 16; c++) {
            const float* tc = tb + (size_t)c * HW;
            float vlt = (vltx && vlty) ? tc[rlt] : 0.f;
            float vrb = (vrbx && vrby) ? tc[rrb] : 0.f;
            float vlb = (vltx && vrby) ? tc[rlb] : 0.f;
            float vrt = (vrbx && vlty) ? tc[rrt] : 0.f;
            float val = glt * vlt + grb * vrb + glb * vlb + grt * vrt;
            const float* wr = &ws[(c * 9 + n) * 16];
            #pragma unroll
            for (int o4 = 0; o4 < 4; o4++) {
                float4 wv = *(const float4*)(wr + 4 * o4);
                acc[4*o4+0] = fmaf(val, wv.x, acc[4*o4+0]);
                acc[4*o4+1] = fmaf(val, wv.y, acc[4*o4+1]);
                acc[4*o4+2] = fmaf(val, wv.z, acc[4*o4+2]);
                acc[4*o4+3] = fmaf(val, wv.w, acc[4*o4+3]);
            }
        }
    }
    #pragma unroll
    for (int o = 0; o < 16; o++) out[(size_t)(b * 16 + o) * HW + pix] = acc[o];
}

// ---------------- CBAM ------------------------------------------------------
__global__ void cbam_reduce_k(const float* __restrict__ x,
                              float* __restrict__ avg, float* __restrict__ mx)
{
    int c = blockIdx.x, b = blockIdx.y;
    const float* xp = x + (size_t)(b * 64 + c) * HW;
    float sm = 0.f, m = -INFINITY;
    for (int k = threadIdx.x; k < HW; k += blockDim.x) {
        float v = xp[k];
        sm += v;
        m = fmaxf(m, v);
    }
    __shared__ float ssm[256], smx[256];
    ssm[threadIdx.x] = sm; smx[threadIdx.x] = m;
    __syncthreads();
    for (int off = 128; off > 0; off >>= 1) {
        if (threadIdx.x < off) {
            ssm[threadIdx.x] += ssm[threadIdx.x + off];
            smx[threadIdx.x] = fmaxf(smx[threadIdx.x], smx[threadIdx.x + off]);
        }
        __syncthreads();
    }
    if (threadIdx.x == 0) {
        avg[b * 64 + c] = ssm[0] / (float)HW;
        mx[b * 64 + c] = smx[0];
    }
}

__global__ void cbam_ca_k(const float* __restrict__ avg, const float* __restrict__ mx,
                          const float* __restrict__ w1, const float* __restrict__ w2,
                          float* __restrict__ ca)
{
    int b = blockIdx.x;
    int tid = threadIdx.x;
    __shared__ float ha[4], hm[4];
    if (tid < 4) {
        float sa = 0.f, sm = 0.f;
        for (int c = 0; c < 64; c++) {
            float wv = w1[tid * 64 + c];
            sa += wv * avg[b * 64 + c];
            sm += wv * mx[b * 64 + c];
        }
        ha[tid] = fmaxf(sa, 0.f);
        hm[tid] = fmaxf(sm, 0.f);
    }
    __syncthreads();
    float va = 0.f, vm = 0.f;
    #pragma unroll
    for (int hh = 0; hh < 4; hh++) {
        float wv = w2[tid * 4 + hh];
        va += wv * ha[hh];
        vm += wv * hm[hh];
    }
    float s = va + vm;
    ca[b * 64 + tid] = 1.f / (1.f + expf(-s));
}

__global__ void cbam_apply1_k(const float* __restrict__ x, const float* __restrict__ ca,
                              float* __restrict__ xo, float* __restrict__ sp)
{
    __shared__ float sca[64];
    int b = blockIdx.y;
    if (threadIdx.x < 64) sca[threadIdx.x] = ca[b * 64 + threadIdx.x];
    __syncthreads();
    int pix = blockIdx.x * blockDim.x + threadIdx.x;
    float sm = 0.f, m = -INFINITY;
    #pragma unroll 1
    for (int c = 0; c < 64; c++) {
        float v = x[(size_t)(b * 64 + c) * HW + pix] * sca[c];
        xo[(size_t)(b * 64 + c) * HW + pix] = v;
        sm += v;
        m = fmaxf(m, v);
    }
    sp[(size_t)(b * 2) * HW + pix] = sm * (1.f / 64.f);
    sp[(size_t)(b * 2 + 1) * HW + pix] = m;
}

__global__ void cbam_apply2_k(const float* __restrict__ sp, const float* __restrict__ wsp,
                              float* __restrict__ xo)
{
    __shared__ float w[98];
    if (threadIdx.x < 98) w[threadIdx.x] = wsp[threadIdx.x];
    __syncthreads();
    int pix = blockIdx.x * blockDim.x + threadIdx.x;
    int b = blockIdx.y;
    int y = pix >> 8, x = pix & 255;
    const float* s0 = sp + (size_t)(b * 2) * HW;
    const float* s1 = s0 + HW;
    float acc = 0.f;
    #pragma unroll 1
    for (int ky = 0; ky < 7; ky++) {
        int yy = y + ky - 3;
        if ((unsigned)yy >= (unsigned)H) continue;
        #pragma unroll
        for (int kx = 0; kx < 7; kx++) {
            int xx = x + kx - 3;
            if ((unsigned)xx >= (unsigned)W) continue;
            int ip = yy * W + xx;
            acc += w[ky * 7 + kx] * s0[ip] + w[49 + ky * 7 + kx] * s1[ip];
        }
    }
    float sg = 1.f / (1.f + expf(-acc));
    #pragma unroll 1
    for (int c = 0; c < 64; c++)
        xo[(size_t)(b * 64 + c) * HW + pix] *= sg;
}

// ---------------- host orchestration ----------------------------------------
extern "C" void kernel_launch(void* const* d_in, const int* in_sizes, int n_in,
                              void* d_out, int out_size)
{
    const float* lf   = (const float*)d_in[0];
    const float* hf   = (const float*)d_in[1];
    const float* w11  = (const float*)d_in[2];
    const float* b11  = (const float*)d_in[3];
    const float* wconv= (const float*)d_in[4];
    const float* woff = (const float*)d_in[5];
    const float* boff = (const float*)d_in[6];
    const float* wdef = (const float*)d_in[7];
    const float* wdil[4] = {(const float*)d_in[8], (const float*)d_in[9],
                            (const float*)d_in[10], (const float*)d_in[11]};
    const float* wc1  = (const float*)d_in[12];
    const float* wc2  = (const float*)d_in[13];
    const float* wfc1 = (const float*)d_in[14];
    const float* wfc2 = (const float*)d_in[15];
    const float* wsp  = (const float*)d_in[16];
    const float* wc12 = (const float*)d_in[17];
    const float* bc12 = (const float*)d_in[18];
    const float* wc33 = (const float*)d_in[19];
    float* out = (float*)d_out;

    void* tmp;
#define GETP(name, sym) cudaGetSymbolAddress(&tmp, sym); float* name = (float*)tmp;
    GETP(p_hf, g_hf)     GETP(p_pre, g_pre)   GETP(p_t, g_t)
    GETP(p_cat, g_cat)   GETP(p_off, g_off)   GETP(p_d16, g_d16)
    GETP(p_d16b, g_d16b) GETP(p_d64, g_d64)   GETP(p_d64b, g_d64b)
    GETP(p_xx, g_xxs)    GETP(p_sp, g_sp)     GETP(p_xb, g_xb)
    GETP(p_psum, g_psum) GETP(p_psq, g_psq)   GETP(p_mean, g_mean)
    GETP(p_inv, g_inv)   GETP(p_avg, g_avg)   GETP(p_gmax, g_gmax)
    GETP(p_ca, g_ca)
#undef GETP
    float* p_x0 = p_xb;
    float* p_x1 = p_xb + SZ16;
    float* p_x2 = p_xb + 2 * (size_t)SZ16;
    float* p_x3 = p_xb + 3 * (size_t)SZ16;

    const dim3 PG(HW / 256, BATCH);
    const int G16 = SZ16 / 256, G32 = SZ32 / 256, G64 = SZ64 / 256;

    auto bnstat = [&](const float* src, int C) {
        stats_part_k<<<dim3(SLICES, C), 256>>>(src, C, p_psum, p_psq);
        stats_final_k<<<1, 64>>>(C, p_psum, p_psq, p_mean, p_inv);
    };

    // Stage A: hf = relu(bn(conv1x1(hf)))
    conv1x1_64_16_k<<<PG, 256>>>(hf, w11, b11, p_pre);
    bnstat(p_pre, 16);
    norm_k<true><<<G16, 256>>>(p_pre, p_hf, 16, SZ16, p_mean, p_inv,
                               nullptr, 0, 0, nullptr, 0, 0);

    struct Desc { const float* p; int ct; int co; };
    Desc prevs[4] = {{lf,64,0},{p_x0,16,0},{p_x1,16,0},{p_x2,16,0}};
    Desc e1[4]    = {{lf,64,16},{p_x0,16,0},{p_x1,16,0},{p_x2,16,0}};
    Desc e2[4]    = {{nullptr,0,0},{lf,64,32},{lf,64,48},{nullptr,0,0}};
    float* outs[4] = {p_x0, p_x1, p_x2, p_x3};

    for (int k = 0; k < 4; k++) {
        // x = bn(conv3x3(cat[prev, hf])); t = x + extra
        cat2_k<<<G32, 256>>>(prevs[k].p, prevs[k].ct, prevs[k].co, p_hf, p_cat);
        conv3x3_k<32,16,false><<<PG, 256>>>(p_cat, 32, 0, wconv, nullptr, p_pre, 1);
        bnstat(p_pre, 16);
        norm_k<false><<<G16, 256>>>(p_pre, p_t, 16, SZ16, p_mean, p_inv,
                                    e1[k].p, e1[k].ct, e1[k].co,
                                    e2[k].p, e2[k].ct, e2[k].co);
        // offsets + deformable conv
        conv3x3_k<16,18,true><<<PG, 256>>>(p_t, 16, 0, woff, boff, p_off, 1);
        deform_k<<<PG, 256>>>(p_t, p_off, wdef, p_d16);
        // dilated conv + bn
        conv3x3_k<16,16,false><<<PG, 256>>>(p_d16, 16, 0, wdil[k], nullptr, p_d16b, k + 1);
        bnstat(p_d16b, 16);
        norm_k<false><<<G16, 256>>>(p_d16b, p_d16, 16, SZ16, p_mean, p_inv,
                                    nullptr, 0, 0, nullptr, 0, 0);
        // 16->64 conv + bn
        conv3x3_k<16,64,false><<<PG, 256>>>(p_d16, 16, 0, wc1, nullptr, p_d64, 1);
        bnstat(p_d64, 64);
        norm_k<false><<<G64, 256>>>(p_d64, p_d64, 64, SZ64, p_mean, p_inv,
                                    nullptr, 0, 0, nullptr, 0, 0);
        // CBAM
        cbam_reduce_k<<<dim3(64, BATCH), 256>>>(p_d64, p_avg, p_gmax);
        cbam_ca_k<<<BATCH, 64>>>(p_avg, p_gmax, wfc1, wfc2, p_ca);
        cbam_apply1_k<<<PG, 256>>>(p_d64, p_ca, p_d64b, p_sp);
        cbam_apply2_k<<<PG, 256>>>(p_sp, wsp, p_d64b);
        // 64->16 conv + bn
        conv3x3_k<64,16,false><<<PG, 256>>>(p_d64b, 64, 0, wc2, nullptr, p_pre, 1);
        bnstat(p_pre, 16);
        norm_k<false><<<G16, 256>>>(p_pre, outs[k], 16, SZ16, p_mean, p_inv,
                                    nullptr, 0, 0, nullptr, 0, 0);
    }

    // xx = relu(bn(conv1x1(cat4))) ; s = lf + xx
    conv1x1_cat4_k<<<PG, 256>>>(p_x0, p_x1, p_x2, p_x3, wc12, bc12, p_d64);
    bnstat(p_d64, 64);
    norm_k<true><<<G64, 256>>>(p_d64, p_xx, 64, SZ64, p_mean, p_inv,
                               lf, 64, 0, nullptr, 0, 0);
    // out = bn(conv3x3(s))
    conv3x3_k<64,64,false><<<PG, 256>>>(p_xx, 64, 0, wc33, nullptr, out, 1);
    bnstat(out, 64);
    norm_k<false><<<G64, 256>>>(out, out, 64, SZ64, p_mean, p_inv,
                                nullptr, 0, 0, nullptr, 0, 0);
}